// round 2
// baseline (speedup 1.0000x reference)
#include <cuda_runtime.h>

#define BB 64
#define VV 2000
#define DD 16
#define CI 64
#define CO 64

// ---------------- scratch (device globals, no allocation) ----------------
__device__ float g_partG[32 * 512];
__device__ float g_inv_norm;
__device__ float g_Zre[BB * DD * CI];
__device__ float g_Zim[BB * DD * CI];
__device__ float g_yre[(size_t)BB * VV * CI];
__device__ float g_yim[(size_t)BB * VV * CI];
__device__ float4 g_AC[(size_t)VV * CI * CO];   // (Ar,Ai,Cr,Ci) per (v,i,o)

// ---------------- f32x2 helpers ----------------
typedef unsigned long long u64t;
__device__ __forceinline__ void fma2(u64t& d, u64t a, u64t b) {
    asm("fma.rn.f32x2 %0, %1, %2, %0;" : "+l"(d) : "l"(a), "l"(b));
}
__device__ __forceinline__ u64t bcast2(float x) {
    u64t r; asm("mov.b64 %0, {%1, %1};" : "=l"(r) : "f"(x)); return r;
}
__device__ __forceinline__ void unpack2(float& lo, float& hi, u64t v) {
    asm("mov.b64 {%0, %1}, %2;" : "=f"(lo), "=f"(hi) : "l"(v));
}

// ---------------- 1a: Gram partials ----------------
__global__ void gram_partial(const float* __restrict__ ner, const float* __restrict__ nei) {
    int blk = blockIdx.x;
    int v0 = blk * 63;
    int cnt = min(63, VV - v0);
    __shared__ float sr[63 * 16], si[63 * 16];
    for (int t = threadIdx.x; t < cnt * 16; t += 256) {
        sr[t] = ner[v0 * 16 + t];
        si[t] = nei[v0 * 16 + t];
    }
    __syncthreads();
    int d = threadIdx.x >> 4, e = threadIdx.x & 15;
    float ar = 0.f, ai = 0.f;
    for (int vv = 0; vv < cnt; vv++) {
        float a = sr[vv * 16 + d], b = si[vv * 16 + d];
        float c = sr[vv * 16 + e], dd = si[vv * 16 + e];
        ar += a * c + b * dd;
        ai += a * dd - b * c;
    }
    g_partG[blk * 512 + threadIdx.x * 2]     = ar;
    g_partG[blk * 512 + threadIdx.x * 2 + 1] = ai;
}

// ---------------- 1b: reduce Gram ----------------
__global__ void gram_reduce() {
    __shared__ float red[256];
    int t = threadIdx.x;
    float gr = 0.f, gi = 0.f;
    for (int blk = 0; blk < 32; blk++) {
        gr += g_partG[blk * 512 + t * 2];
        gi += g_partG[blk * 512 + t * 2 + 1];
    }
    red[t] = gr * gr + gi * gi;
    __syncthreads();
    for (int s = 128; s > 0; s >>= 1) {
        if (t < s) red[t] += red[t + s];
        __syncthreads();
    }
    if (t == 0) g_inv_norm = rsqrtf(red[0]);
}

// ---------------- 2: Z[b,d,i] = sum_v conj(ne[v,d]) * x[b,v,i] ----------------
__global__ void __launch_bounds__(256) z_kernel(const float* __restrict__ x,
                                                const float* __restrict__ ner,
                                                const float* __restrict__ nei) {
    int b = blockIdx.y;
    int d0 = blockIdx.x * 4;
    int i = threadIdx.x & 63;
    int dl = threadIdx.x >> 6;
    __shared__ float xs[64 * 64];
    __shared__ float nr[64 * 4], ni[64 * 4];
    float ar = 0.f, ai = 0.f;
    for (int v0 = 0; v0 < VV; v0 += 64) {
        int cnt = min(64, VV - v0);
        __syncthreads();
        for (int t = threadIdx.x; t < cnt * 64; t += 256)
            xs[t] = x[(size_t)b * VV * 64 + (size_t)v0 * 64 + t];
        for (int t = threadIdx.x; t < cnt * 4; t += 256) {
            int vv = t >> 2, dd = t & 3;
            nr[t] = ner[(v0 + vv) * 16 + d0 + dd];
            ni[t] = nei[(v0 + vv) * 16 + d0 + dd];
        }
        __syncthreads();
        for (int vv = 0; vv < cnt; vv++) {
            float xv = xs[vv * 64 + i];
            ar += nr[vv * 4 + dl] * xv;
            ai -= ni[vv * 4 + dl] * xv;
        }
    }
    g_Zre[(b * 16 + d0 + dl) * 64 + i] = ar;
    g_Zim[(b * 16 + d0 + dl) * 64 + i] = ai;
}

// ---------------- 3: y[b,v,i] = sum_d ne[v,d] * Z[b,d,i] ----------------
__global__ void __launch_bounds__(256) y_kernel(const float* __restrict__ ner,
                                                const float* __restrict__ nei) {
    int b = blockIdx.y;
    int v0 = blockIdx.x * 64;
    int vcnt = min(64, VV - v0);
    __shared__ float Zr[16 * 64], Zi[16 * 64], nr[64 * 16], ni[64 * 16];
    for (int t = threadIdx.x; t < 1024; t += 256) {
        Zr[t] = g_Zre[b * 1024 + t];
        Zi[t] = g_Zim[b * 1024 + t];
    }
    for (int t = threadIdx.x; t < vcnt * 16; t += 256) {
        nr[t] = ner[v0 * 16 + t];
        ni[t] = nei[v0 * 16 + t];
    }
    __syncthreads();
    int i = threadIdx.x & 63;
    int vb = threadIdx.x >> 6;
    float zr[16], zi[16];
#pragma unroll
    for (int d = 0; d < 16; d++) { zr[d] = Zr[d * 64 + i]; zi[d] = Zi[d * 64 + i]; }
    for (int vl = vb; vl < vcnt; vl += 4) {
        float yr = 0.f, yi = 0.f;
#pragma unroll
        for (int d = 0; d < 16; d++) {
            float a = nr[vl * 16 + d], c = ni[vl * 16 + d];
            yr += a * zr[d] - c * zi[d];
            yi += a * zi[d] + c * zr[d];
        }
        size_t o = (size_t)b * VV * 64 + (size_t)(v0 + vl) * 64 + i;
        g_yre[o] = yr;
        g_yim[o] = yi;
    }
}

// ---------------- 4: combined per-node weights, interleaved float4 ----------------
__global__ void __launch_bounds__(256) wcomb_kernel(const float* __restrict__ ner,
                                                    const float* __restrict__ nei,
                                                    const float* __restrict__ wr,
                                                    const float* __restrict__ wi) {
    int io = blockIdx.x * 256 + threadIdx.x;   // 0..4095 (i*64+o)
    int vstart = blockIdx.y * 100;
    float s = g_inv_norm;
    float P0r[16], P0i[16], P1r[16], P1i[16];
#pragma unroll
    for (int d = 0; d < 16; d++) {
        float r0 = wr[(d * 3 + 0) * 4096 + io];
        float r1 = wr[(d * 3 + 1) * 4096 + io];
        float r2 = wr[(d * 3 + 2) * 4096 + io];
        float i0 = wi[(d * 3 + 0) * 4096 + io];
        float i1 = wi[(d * 3 + 1) * 4096 + io];
        float i2 = wi[(d * 3 + 2) * 4096 + io];
        P0r[d] = r0 - r2;
        P0i[d] = i0 - i2;
        P1r[d] = (r1 + 2.f * r2) * s;
        P1i[d] = (i1 + 2.f * i2) * s;
    }
    __shared__ float nr[100 * 16], ni[100 * 16];
    for (int t = threadIdx.x; t < 100 * 16; t += 256) {
        nr[t] = ner[vstart * 16 + t];
        ni[t] = nei[vstart * 16 + t];
    }
    __syncthreads();
    for (int vl = 0; vl < 100; vl++) {
        float Ar = 0.f, Ai = 0.f, Cr = 0.f, Ci = 0.f;
#pragma unroll
        for (int d = 0; d < 16; d++) {
            float a = nr[vl * 16 + d], b = ni[vl * 16 + d];
            Ar += a * P0r[d] - b * P0i[d];
            Ai += a * P0i[d] + b * P0r[d];
            Cr += a * P1r[d] - b * P1i[d];
            Ci += a * P1i[d] + b * P1r[d];
        }
        g_AC[(size_t)(vstart + vl) * 4096 + io] = make_float4(Ar, Ai, Cr, Ci);
    }
}

// ---------------- 5: final per-node GEMM with packed f32x2 ----------------
// Block = (v, o-half). 128 threads. Thread tile: 4 b-pairs (8 b) x 2 o.
// out_re = x*Ar + yr*Cr - yi*Ci ; out_im = x*Ai + yr*Ci + yi*Cr
#define XROW 66   // padded smem row stride (floats), even -> 8B aligned pairs

__global__ void __launch_bounds__(128) out2_kernel(const float* __restrict__ x,
                                                   const float* __restrict__ ner,
                                                   const float* __restrict__ nei,
                                                   const float* __restrict__ bre,
                                                   const float* __restrict__ bim,
                                                   float* __restrict__ out) {
    extern __shared__ float sm[];
    float4* acs = (float4*)sm;                 // 64 i x 32 o  (8192 floats)
    float* xs  = sm + 8192;                    // [i][b] 64*66
    float* yrs = sm + 8192 + 64 * XROW;
    float* yis = sm + 8192 + 2 * 64 * XROW;
    float2* bs = (float2*)(sm + 8192 + 3 * 64 * XROW);  // 32 o-pairs

    int oh = blockIdx.x;       // o-half: 0 or 1
    int v  = blockIdx.y;
    int tid = threadIdx.x;

    // ---- fill coefficients (o-half slice) ----
    const float4* g4 = g_AC + (size_t)v * 4096 + oh * 32;
    for (int n = tid; n < 2048; n += 128) {
        int i = n >> 5, o = n & 31;
        acs[n] = g4[i * 64 + o];
    }
    // ---- fill x / y transposed to [i][b] ----
    for (int n = tid; n < 4096; n += 128) {
        int b = n >> 6, i = n & 63;
        size_t go = ((size_t)b * VV + v) * 64 + i;
        xs[i * XROW + b]  = x[go];
        yrs[i * XROW + b] = g_yre[go];
        yis[i * XROW + b] = g_yim[go];
    }
    // ---- bias for this o-half ----
    if (tid < 32) {
        int o = oh * 32 + tid;
        float r = 0.f, m = 0.f;
#pragma unroll
        for (int d = 0; d < 16; d++) {
            float a = ner[v * 16 + d], b2 = nei[v * 16 + d];
            float pr = bre[d * 64 + o], pi = bim[d * 64 + o];
            r += a * pr - b2 * pi;
            m += a * pi + b2 * pr;
        }
        bs[tid] = make_float2(r, m);
    }
    __syncthreads();

    int og = tid & 15;     // o-pair group: local o = og*2 + {0,1}
    int pg = tid >> 4;     // 0..7 -> b base = pg*8, 4 pairs

    u64t accP[4][2] = {}, accN[4][2] = {}, accIm[4][2] = {};

#pragma unroll 2
    for (int i = 0; i < 64; i++) {
        float4 c0 = acs[i * 32 + og * 2];
        float4 c1 = acs[i * 32 + og * 2 + 1];
        u64t arP[2] = { bcast2(c0.x), bcast2(c1.x) };
        u64t aiP[2] = { bcast2(c0.y), bcast2(c1.y) };
        u64t crP[2] = { bcast2(c0.z), bcast2(c1.z) };
        u64t ciP[2] = { bcast2(c0.w), bcast2(c1.w) };
        const float* xr  = xs  + i * XROW + pg * 8;
        const float* yrr = yrs + i * XROW + pg * 8;
        const float* yir = yis + i * XROW + pg * 8;
#pragma unroll
        for (int k = 0; k < 4; k++) {
            u64t xp  = *(const u64t*)(xr  + 2 * k);
            u64t yrp = *(const u64t*)(yrr + 2 * k);
            u64t yip = *(const u64t*)(yir + 2 * k);
#pragma unroll
            for (int ol = 0; ol < 2; ol++) {
                fma2(accP[k][ol], xp,  arP[ol]);
                fma2(accP[k][ol], yrp, crP[ol]);
                fma2(accN[k][ol], yip, ciP[ol]);
                fma2(accIm[k][ol], xp,  aiP[ol]);
                fma2(accIm[k][ol], yrp, ciP[ol]);
                fma2(accIm[k][ol], yip, crP[ol]);
            }
        }
    }

    // ---- epilogue: re = accP - accN (via fma with -1 pair), add bias, store interleaved ----
    const u64t NEG1 = 0xBF800000BF800000ULL;   // (-1.0f, -1.0f)
    float2 b0v = bs[og * 2], b1v = bs[og * 2 + 1];
    size_t obase = ((size_t)(pg * 8) * VV + v) * 128 + (size_t)(oh * 64 + og * 4);
#pragma unroll
    for (int k = 0; k < 4; k++) {
        u64t re0 = accP[k][0]; fma2(re0, accN[k][0], NEG1);
        u64t re1 = accP[k][1]; fma2(re1, accN[k][1], NEG1);
        float r0a, r0b, r1a, r1b, i0a, i0b, i1a, i1b;
        unpack2(r0a, r0b, re0);
        unpack2(r1a, r1b, re1);
        unpack2(i0a, i0b, accIm[k][0]);
        unpack2(i1a, i1b, accIm[k][1]);
        // b = pg*8 + 2k (lane a) and +1 (lane b)
        size_t oA = obase + (size_t)(2 * k) * (VV * 128);
        size_t oB = oA + (size_t)(VV * 128);
        *(float4*)(out + oA) = make_float4(r0a + b0v.x, i0a + b0v.y, r1a + b1v.x, i1a + b1v.y);
        *(float4*)(out + oB) = make_float4(r0b + b0v.x, i0b + b0v.y, r1b + b1v.x, i1b + b1v.y);
    }
}

extern "C" void kernel_launch(void* const* d_in, const int* in_sizes, int n_in,
                              void* d_out, int out_size) {
    const float* x   = (const float*)d_in[0];
    const float* ner = (const float*)d_in[1];
    const float* nei = (const float*)d_in[2];
    const float* wr  = (const float*)d_in[3];
    const float* wi  = (const float*)d_in[4];
    const float* bre = (const float*)d_in[5];
    const float* bim = (const float*)d_in[6];
    float* out = (float*)d_out;

    int smem_out = (8192 + 3 * 64 * XROW + 64) * 4;
    cudaFuncSetAttribute(out2_kernel, cudaFuncAttributeMaxDynamicSharedMemorySize, smem_out);

    gram_partial<<<32, 256>>>(ner, nei);
    gram_reduce<<<1, 256>>>();
    z_kernel<<<dim3(4, BB), 256>>>(x, ner, nei);
    y_kernel<<<dim3(32, BB), 256>>>(ner, nei);
    wcomb_kernel<<<dim3(16, 20), 256>>>(ner, nei, wr, wi);
    out2_kernel<<<dim3(2, VV), 128, smem_out>>>(x, ner, nei, bre, bim, out);
}